// round 8
// baseline (speedup 1.0000x reference)
#include <cuda_runtime.h>
#include <math.h>

// Problem constants (fixed shapes from reference setup_inputs)
#define BN   32
#define NA   24564
#define NCLS 81
#define NO   16
#define TOTROWS (BN * NA)   // 786048

#define HSHIFT 17
#define HBINS  32768        // 15-bit float-bits prefix per batch

// ---------------- scratch (device globals: no allocation allowed) ----------
__device__ float              g_negconf[BN * NA];
__device__ unsigned           g_hist[BN * HBINS];  // built inside k_conf
__device__ int2               g_argm[BN * NA];     // per-anchor (biou bits, best obj)
__device__ unsigned long long g_best[BN * NO];
__device__ int                g_npos[BN];
__device__ int                g_npos_total;
__device__ int                g_done;
__device__ double             g_posconf;
__device__ double             g_sl1;
__device__ double             g_hard;

// ---------------- init: zero hist (1M ints) + small state ------------------
__global__ void k_init() {
    unsigned gid = blockIdx.x * 1024u + threadIdx.x;   // grid = 1024 x 1024
    if (gid < BN * HBINS) g_hist[gid] = 0u;
    if (blockIdx.x == 0) {
        int i = threadIdx.x;
        if (i < BN * NO) g_best[i] = 0ull;
        if (i < BN)      g_npos[i] = 0;
        if (i == 0) {
            g_npos_total = 0; g_done = 0;
            g_posconf = 0.0; g_sl1 = 0.0; g_hard = 0.0;
        }
    }
}

// IoU in the exact op order of the reference (max/min/clip/mul/div)
__device__ __forceinline__ float iou_xy(
    float ax0, float ay0, float ax1, float ay1, float areaA,
    float dx0, float dy0, float dx1, float dy1, float areaB)
{
    float ltx = fmaxf(ax0, dx0), lty = fmaxf(ay0, dy0);
    float rbx = fminf(ax1, dx1), rby = fminf(ay1, dy1);
    float w = fmaxf(rbx - ltx, 0.0f), h = fmaxf(rby - lty, 0.0f);
    float inter = w * h;
    return inter / (areaA + areaB - inter);
}

// ---------------- fused match pass A ---------------------------------------
#define MA_T 256
__global__ void __launch_bounds__(MA_T) k_matchA(const float4* __restrict__ boxes,
                                                 const float4* __restrict__ dboxes)
{
    int b = blockIdx.y;
    int n = blockIdx.x * MA_T + threadIdx.x;

    __shared__ float4 sbox[NO];
    __shared__ float  sarea[NO];
    __shared__ unsigned long long sb[NO];
    if (threadIdx.x < NO) {
        float4 bx = boxes[b * NO + threadIdx.x];
        sbox[threadIdx.x]  = bx;
        sarea[threadIdx.x] = (bx.z - bx.x) * (bx.w - bx.y);
        sb[threadIdx.x]    = 0ull;
    }
    __syncthreads();

    if (n < NA) {
        float4 d = __ldg(&dboxes[n]);
        float dx0 = d.x - d.z / 2.0f, dy0 = d.y - d.w / 2.0f;
        float dx1 = d.x + d.z / 2.0f, dy1 = d.y + d.w / 2.0f;
        float areaB = (dx1 - dx0) * (dy1 - dy0);

        float biou = -1.0f; int bo = 0;
#pragma unroll
        for (int o = 0; o < NO; o++) {
            float4 a = sbox[o];
            float v = iou_xy(a.x, a.y, a.z, a.w, sarea[o], dx0, dy0, dx1, dy1, areaB);
            if (v > biou) { biou = v; bo = o; }      // strict > : first max wins
            unsigned long long key =
                ((unsigned long long)__float_as_uint(v) << 32) |
                (unsigned long long)(0xFFFFFFFFu - (unsigned)n);
            if (key > sb[o]) atomicMax(&sb[o], key); // guarded: skip hopeless
        }
        g_argm[b * NA + n] = make_int2(__float_as_int(biou), bo);
    }
    __syncthreads();
    if (threadIdx.x < NO) {
        unsigned long long k = sb[threadIdx.x];
        if (k > g_best[b * NO + threadIdx.x])
            atomicMax(&g_best[b * NO + threadIdx.x], k);
    }
}

// ------- fused: match-B + softmax conf + loc loss + selection histogram ----
#define B_T  256
#define RPW  4

__global__ void __launch_bounds__(B_T) k_conf(const float*  __restrict__ cls,
                                              const float*  __restrict__ locs,
                                              const float4* __restrict__ boxes,
                                              const int*    __restrict__ labels,
                                              const float4* __restrict__ dboxes)
{
    const unsigned FULL = 0xffffffffu;
    int wg   = (blockIdx.x * B_T + threadIdx.x) >> 5;   // global warp id
    int lane = threadIdx.x & 31;
    int wip  = threadIdx.x >> 5;
    int row0 = wg * RPW;
    int b    = row0 / NA;          // warp-uniform
    int n0   = row0 - b * NA;

    float4   obox = make_float4(0.f, 0.f, 0.f, 0.f);
    int      olab = 0;
    unsigned osov = 0xFFFFFFFFu;
    if (lane < NO) {
        obox = __ldg(&boxes[b * NO + lane]);
        olab = __ldg(&labels[b * NO + lane]);
        unsigned long long be = g_best[b * NO + lane];
        osov = 0xFFFFFFFFu - (unsigned)(be & 0xFFFFFFFFull);
    }
    int2 am = make_int2(0, 0);
    if (lane < RPW) am = g_argm[row0 + lane];

    // -------- softmax logits (the HBM-dominant part) --------
    const float* p = cls + (size_t)row0 * NCLS;
    float v0[RPW], v1[RPW], v2[RPW];
#pragma unroll
    for (int r = 0; r < RPW; r++) {                      // 12 front-batched LDGs
        v0[r] = __ldg(p + r * NCLS + lane);
        v1[r] = __ldg(p + r * NCLS + 32 + lane);
        v2[r] = (lane < 17) ? __ldg(p + r * NCLS + 64 + lane) : 0.0f;
    }
    float s[RPW];
#pragma unroll
    for (int r = 0; r < RPW; r++)
        s[r] = __expf(v0[r]) + __expf(v1[r]) +
               ((lane < 17) ? __expf(v2[r]) : 0.0f);
#pragma unroll
    for (int o = 16; o > 0; o >>= 1) {                   // 4 interleaved chains
#pragma unroll
        for (int r = 0; r < RPW; r++)
            s[r] += __shfl_xor_sync(FULL, s[r], o);
    }

    // -------- match-B: labels in-register --------
    int   lbl[RPW];
    int   bo_[RPW];
    float nc[RPW];
#pragma unroll
    for (int r = 0; r < RPW; r++) {
        int n_r = n0 + r;
        int ax  = __shfl_sync(FULL, am.x, r);
        int ay  = __shfl_sync(FULL, am.y, r);
        unsigned bal = __ballot_sync(FULL, lane < NO && osov == (unsigned)n_r);
        int   bo;  float biou;
        if (bal) { bo = 31 - __clz(bal); biou = 1.0f; }  // highest o = last write
        else     { bo = ay; biou = __int_as_float(ax); }
        int l = (biou < 0.5f) ? 0 : __shfl_sync(FULL, olab, bo);
        lbl[r] = l; bo_[r] = bo;
    }

#pragma unroll
    for (int r = 0; r < RPW; r++) {
        float sel = (lbl[r] < 32) ? v0[r] : ((lbl[r] < 64) ? v1[r] : v2[r]);
        float logit = __shfl_sync(FULL, sel, lbl[r] & 31);
        float conf  = __logf(s[r]) - logit;
        nc[r] = (lbl[r] != 0) ? -conf : conf;            // positives stash -conf
    }

    // -------- positives: loc loss + pos_conf (rare path, warp-uniform) -----
    __shared__ float sp[B_T / 32], ss[B_T / 32];
    float myp = 0.0f, mys = 0.0f;
    int cnt = 0;
#pragma unroll
    for (int r = 0; r < RPW; r++) {
        if (lbl[r] != 0) {                               // warp-uniform condition
            cnt++;
            float ax0 = __shfl_sync(FULL, obox.x, bo_[r]);
            float ay0 = __shfl_sync(FULL, obox.y, bo_[r]);
            float ax1 = __shfl_sync(FULL, obox.z, bo_[r]);
            float ay1 = __shfl_sync(FULL, obox.w, bo_[r]);
            float4 d  = __ldg(&dboxes[n0 + r]);
            float bcx = (ax1 + ax0) / 2.0f, bcy = (ay1 + ay0) / 2.0f;
            float bw  = ax1 - ax0,          bh  = ay1 - ay0;
            float tx = (bcx - d.x) / (d.z / 10.0f + 1e-6f);
            float ty = (bcy - d.y) / (d.w / 10.0f + 1e-6f);
            float tz = logf(bw / d.z + 1e-6f) * 5.0f;
            float tw = logf(bh / d.w + 1e-6f) * 5.0f;
            if (lane == 0) {
                myp += -nc[r];                           // recover conf
                float4 lp = __ldg((const float4*)(locs + (size_t)(row0 + r) * 4));
                float acc = 0.0f, dd;
                dd = fabsf(lp.x - tx); acc += (dd < 1.0f) ? 0.5f * dd * dd : dd - 0.5f;
                dd = fabsf(lp.y - ty); acc += (dd < 1.0f) ? 0.5f * dd * dd : dd - 0.5f;
                dd = fabsf(lp.z - tz); acc += (dd < 1.0f) ? 0.5f * dd * dd : dd - 0.5f;
                dd = fabsf(lp.w - tw); acc += (dd < 1.0f) ? 0.5f * dd * dd : dd - 0.5f;
                mys += acc;
            }
            nc[r] = 0.0f;                                // negconf = 0 for positives
        }
    }
    if (lane == 0) {
        ((float4*)g_negconf)[wg] = make_float4(nc[0], nc[1], nc[2], nc[3]);
        // selection histogram as a side effect (hidden under HBM traffic)
        unsigned* H = &g_hist[b * HBINS];
#pragma unroll
        for (int r = 0; r < RPW; r++)
            atomicAdd(&H[__float_as_uint(nc[r]) >> HSHIFT], 1u);
        sp[wip] = myp; ss[wip] = mys;
        if (cnt) {
            atomicAdd(&g_npos[b], cnt);
            atomicAdd(&g_npos_total, cnt);
        }
    }
    __syncthreads();
    if (threadIdx.x == 0) {
        float tp = 0.0f, ts = 0.0f;
#pragma unroll
        for (int i = 0; i < B_T / 32; i++) { tp += sp[i]; ts += ss[i]; }
        if (tp != 0.0f) atomicAdd(&g_posconf, (double)tp);
        if (ts != 0.0f) atomicAdd(&g_sl1, (double)ts);
    }
}

// ---------------- top-k: 1 sweep + parallel scans ---------------------------
#define C_T   1024
#define NA4   (NA / 4)     // 6141 exactly
#define BUFSZ 2048

// returns sum of 'val' over all threads with tid' > tid (block-wide).
// Must be called by ALL C_T threads (uniform control). tmp32: shared[32].
__device__ __forceinline__ int block_suffix_after(int val, int tid, int* tmp32)
{
    const unsigned FULL = 0xffffffffu;
    int lane = tid & 31, w = tid >> 5;
    __syncthreads();                       // protect tmp32 reuse
    int s = val;                           // inclusive suffix within warp
#pragma unroll
    for (int o = 1; o < 32; o <<= 1) {
        int v = __shfl_down_sync(FULL, s, o);
        if (lane + o < 32) s += v;
    }
    if (lane == 0) tmp32[w] = s;           // warp totals
    __syncthreads();
    if (tid < 32) {
        int wv = tmp32[tid];
        int t2 = wv;
#pragma unroll
        for (int o = 1; o < 32; o <<= 1) {
            int v = __shfl_down_sync(FULL, t2, o);
            if (lane + o < 32) t2 += v;
        }
        tmp32[tid] = t2 - wv;              // suffix strictly after warp tid
    }
    __syncthreads();
    return tmp32[w] + (s - val);           // after-warp + higher lanes in warp
}

__global__ void __launch_bounds__(C_T) k_topk(float* __restrict__ out)
{
    int b = blockIdx.x;
    int tid = threadIdx.x;
    __shared__ int      tmp32[32];
    __shared__ unsigned sbuf[BUFSZ];
    __shared__ int      s_m, s_B, s_rem, s_d1, s_r1, s_d2, s_last;
    __shared__ unsigned cnt[512];
    __shared__ double   sdbl[32];
    __shared__ int      sint[32];

    int k = 3 * g_npos[b];
    if (k > NA) k = NA;

    if (k > 0) {
        // ---- stage 1: boundary bin from precomputed histogram (no sweep) ----
        const unsigned* H = &g_hist[b * HBINS];
        int base = tid * (HBINS / C_T);                  // 32 bins per thread
        int mysum = 0;
#pragma unroll 8
        for (int i = 0; i < HBINS / C_T; i++) mysum += (int)H[base + i];
        int sufA = block_suffix_after(mysum, tid, tmp32);
        if (tid == 0) s_m = 0;
        if (sufA < k && sufA + mysum >= k) {             // exactly one thread
            int r = k - sufA;
            for (int i = HBINS / C_T - 1; i >= 0; --i) {
                int c = (int)H[base + i];
                if (r <= c) { s_B = base + i; s_rem = r; break; }
                r -= c;
            }
        }
        __syncthreads();
        int B = s_B, rem = s_rem;

        // ---- stage 2: the single data sweep ----
        const float4* v4 = (const float4*)&g_negconf[b * NA];
        double sg = 0.0;
        for (int j = tid; j < NA4; j += C_T) {           // ragged ok: no collectives
            float4 x = __ldg(&v4[j]);
            float vv[4] = {x.x, x.y, x.z, x.w};
#pragma unroll
            for (int c = 0; c < 4; c++) {
                unsigned bits = __float_as_uint(vv[c]);
                int bin = (int)(bits >> HSHIFT);
                if (bin > B) sg += (double)vv[c];
                else if (bin == B) {
                    int pos = atomicAdd(&s_m, 1);
                    if (pos < BUFSZ) sbuf[pos] = bits;
                }
            }
        }
        // block-reduce sg -> s_sumhi (uniform collectives)
#pragma unroll
        for (int o = 16; o > 0; o >>= 1) sg += __shfl_xor_sync(0xffffffffu, sg, o);
        if ((tid & 31) == 0) sdbl[tid >> 5] = sg;
        __syncthreads();
        double sumhi = 0.0;
        if (tid == 0) {
#pragma unroll
            for (int i = 0; i < 32; i++) sumhi += sdbl[i];
        }
        int m = s_m; if (m > BUFSZ) m = BUFSZ;

        // ---- stage 3: exact mini radix-select over boundary-bin elements ----
        // low 17 bits; pass1 = 9 bits (512 bins), pass2 = 8 bits (256 bins)
        if (tid < 512) cnt[tid] = 0;
        __syncthreads();
        for (int j = tid; j < m; j += C_T)
            atomicAdd(&cnt[(sbuf[j] >> 8) & 0x1FFu], 1u);
        __syncthreads();
        int myc = (tid < 512) ? (int)cnt[tid] : 0;
        sufA = block_suffix_after(myc, tid, tmp32);
        if (tid < 512 && sufA < rem && sufA + myc >= rem) {
            s_d1 = tid; s_r1 = rem - sufA;
        }
        __syncthreads();
        int d1 = s_d1, r1 = s_r1;
        if (tid < 256) cnt[tid] = 0;
        __syncthreads();
        for (int j = tid; j < m; j += C_T) {
            unsigned bb = sbuf[j];
            if (((bb >> 8) & 0x1FFu) == (unsigned)d1)
                atomicAdd(&cnt[bb & 255u], 1u);
        }
        __syncthreads();
        myc = (tid < 256) ? (int)cnt[tid] : 0;
        sufA = block_suffix_after(myc, tid, tmp32);
        if (tid < 256 && sufA < r1 && sufA + myc >= r1) s_d2 = tid;
        __syncthreads();
        unsigned tbits = ((unsigned)B << HSHIFT) | ((unsigned)d1 << 8) | (unsigned)s_d2;

        // ---- stage 4: exact sum with tie handling ----
        double sb = 0.0; int cb = 0;
        for (int j = tid; j < m; j += C_T) {
            unsigned bb = sbuf[j];
            if (bb > tbits) { sb += (double)__uint_as_float(bb); cb++; }
        }
#pragma unroll
        for (int o = 16; o > 0; o >>= 1) {
            sb += __shfl_xor_sync(0xffffffffu, sb, o);
            cb += __shfl_xor_sync(0xffffffffu, cb, o);
        }
        if ((tid & 31) == 0) { sdbl[tid >> 5] = sb; sint[tid >> 5] = cb; }
        __syncthreads();
        if (tid == 0) {
            double sb2 = 0.0; int cb2 = 0;
#pragma unroll
            for (int i = 0; i < 32; i++) { sb2 += sdbl[i]; cb2 += sint[i]; }
            double t = (double)__uint_as_float(tbits);
            atomicAdd(&g_hard, sumhi + sb2 + (double)(rem - cb2) * t);
        }
    }

    // completion ticket: last block finalizes the scalar loss
    __threadfence();
    if (tid == 0) {
        int t = atomicAdd(&g_done, 1);
        s_last = (t == BN - 1);
    }
    __syncthreads();
    if (tid == 0 && s_last) {
        double npt  = (double)(*(volatile int*)&g_npos_total);
        double sl1  = *(volatile double*)&g_sl1;
        double pc   = *(volatile double*)&g_posconf;
        double hd   = *(volatile double*)&g_hard;
        double loc  = sl1 / (npt * 4.0);
        double conf = (hd + pc) / npt;
        out[0] = (float)(0.5 * loc + conf);
    }
}

// ---------------- launcher --------------------------------------------------
extern "C" void kernel_launch(void* const* d_in, const int* in_sizes, int n_in,
                              void* d_out, int out_size)
{
    (void)in_sizes; (void)n_in; (void)out_size;
    const float*  locs   = (const float*)d_in[0];
    const float*  cls    = (const float*)d_in[1];
    const float4* boxes  = (const float4*)d_in[2];
    const int*    labels = (const int*)d_in[3];
    const float4* dboxes = (const float4*)d_in[4];

    k_init<<<(BN * HBINS) / 1024, 1024>>>();
    dim3 gm((NA + MA_T - 1) / MA_T, BN);
    k_matchA<<<gm, MA_T>>>(boxes, dboxes);
    int blocksB = TOTROWS / (RPW * (B_T / 32));   // 24564, exact
    k_conf<<<blocksB, B_T>>>(cls, locs, boxes, labels, dboxes);
    k_topk<<<BN, C_T>>>((float*)d_out);
}

// round 9
// speedup vs baseline: 1.7544x; 1.7544x over previous
#include <cuda_runtime.h>
#include <math.h>

// Problem constants (fixed shapes from reference setup_inputs)
#define BN   32
#define NA   24564
#define NCLS 81
#define NO   16
#define TOTROWS (BN * NA)   // 786048

// ---------------- scratch (device globals: no allocation allowed) ----------
__device__ float              g_negconf[BN * NA];
__device__ int2               g_argm[BN * NA];     // per-anchor (biou bits, best obj)
__device__ unsigned long long g_best[BN * NO];
__device__ int                g_npos[BN];
__device__ int                g_npos_total;
__device__ int                g_done;
__device__ double             g_posconf;
__device__ double             g_sl1;
__device__ double             g_hard;

// ---------------- init --------------------------------------------------
__global__ void k_init() {
    int i = threadIdx.x;
    if (i < BN * NO) g_best[i] = 0ull;
    if (i < BN)      g_npos[i] = 0;
    if (i == 0) {
        g_npos_total = 0; g_done = 0;
        g_posconf = 0.0; g_sl1 = 0.0; g_hard = 0.0;
    }
}

// IoU in the exact op order of the reference (max/min/clip/mul/div)
__device__ __forceinline__ float iou_xy(
    float ax0, float ay0, float ax1, float ay1, float areaA,
    float dx0, float dy0, float dx1, float dy1, float areaB)
{
    float ltx = fmaxf(ax0, dx0), lty = fmaxf(ay0, dy0);
    float rbx = fminf(ax1, dx1), rby = fminf(ay1, dy1);
    float w = fmaxf(rbx - ltx, 0.0f), h = fmaxf(rby - lty, 0.0f);
    float inter = w * h;
    return inter / (areaA + areaB - inter);
}

// ---------------- fused match pass A ---------------------------------------
#define MA_T 256
__global__ void __launch_bounds__(MA_T) k_matchA(const float4* __restrict__ boxes,
                                                 const float4* __restrict__ dboxes)
{
    int b = blockIdx.y;
    int n = blockIdx.x * MA_T + threadIdx.x;

    __shared__ float4 sbox[NO];
    __shared__ float  sarea[NO];
    __shared__ unsigned long long sb[NO];
    if (threadIdx.x < NO) {
        float4 bx = boxes[b * NO + threadIdx.x];
        sbox[threadIdx.x]  = bx;
        sarea[threadIdx.x] = (bx.z - bx.x) * (bx.w - bx.y);
        sb[threadIdx.x]    = 0ull;
    }
    __syncthreads();

    if (n < NA) {
        float4 d = __ldg(&dboxes[n]);
        float dx0 = d.x - d.z / 2.0f, dy0 = d.y - d.w / 2.0f;
        float dx1 = d.x + d.z / 2.0f, dy1 = d.y + d.w / 2.0f;
        float areaB = (dx1 - dx0) * (dy1 - dy0);

        float biou = -1.0f; int bo = 0;
#pragma unroll
        for (int o = 0; o < NO; o++) {
            float4 a = sbox[o];
            float v = iou_xy(a.x, a.y, a.z, a.w, sarea[o], dx0, dy0, dx1, dy1, areaB);
            if (v > biou) { biou = v; bo = o; }      // strict > : first max wins
            unsigned long long key =
                ((unsigned long long)__float_as_uint(v) << 32) |
                (unsigned long long)(0xFFFFFFFFu - (unsigned)n);
            if (key > sb[o]) atomicMax(&sb[o], key); // guarded: skip hopeless
        }
        g_argm[b * NA + n] = make_int2(__float_as_int(biou), bo);
    }
    __syncthreads();
    if (threadIdx.x < NO) {
        unsigned long long k = sb[threadIdx.x];
        if (k > g_best[b * NO + threadIdx.x])
            atomicMax(&g_best[b * NO + threadIdx.x], k);
    }
}

// ------- fused: match-B (override/label/encode) + softmax conf + loc loss --
#define B_T  256
#define RPW  4

__global__ void __launch_bounds__(B_T) k_conf(const float*  __restrict__ cls,
                                              const float*  __restrict__ locs,
                                              const float4* __restrict__ boxes,
                                              const int*    __restrict__ labels,
                                              const float4* __restrict__ dboxes)
{
    const unsigned FULL = 0xffffffffu;
    int wg   = (blockIdx.x * B_T + threadIdx.x) >> 5;   // global warp id
    int lane = threadIdx.x & 31;
    int wip  = threadIdx.x >> 5;
    int row0 = wg * RPW;
    int b    = row0 / NA;          // warp-uniform
    int n0   = row0 - b * NA;

    float4   obox = make_float4(0.f, 0.f, 0.f, 0.f);
    int      olab = 0;
    unsigned osov = 0xFFFFFFFFu;
    if (lane < NO) {
        obox = __ldg(&boxes[b * NO + lane]);
        olab = __ldg(&labels[b * NO + lane]);
        unsigned long long be = g_best[b * NO + lane];
        osov = 0xFFFFFFFFu - (unsigned)(be & 0xFFFFFFFFull);
    }
    int2 am = make_int2(0, 0);
    if (lane < RPW) am = g_argm[row0 + lane];

    // -------- softmax logits (the HBM-dominant part) --------
    const float* p = cls + (size_t)row0 * NCLS;
    float v0[RPW], v1[RPW], v2[RPW];
#pragma unroll
    for (int r = 0; r < RPW; r++) {                      // 12 front-batched LDGs
        v0[r] = __ldg(p + r * NCLS + lane);
        v1[r] = __ldg(p + r * NCLS + 32 + lane);
        v2[r] = (lane < 17) ? __ldg(p + r * NCLS + 64 + lane) : 0.0f;
    }
    float s[RPW];
#pragma unroll
    for (int r = 0; r < RPW; r++)
        s[r] = __expf(v0[r]) + __expf(v1[r]) +
               ((lane < 17) ? __expf(v2[r]) : 0.0f);
#pragma unroll
    for (int o = 16; o > 0; o >>= 1) {                   // 4 interleaved chains
#pragma unroll
        for (int r = 0; r < RPW; r++)
            s[r] += __shfl_xor_sync(FULL, s[r], o);
    }

    // -------- match-B: labels in-register --------
    int   lbl[RPW];
    int   bo_[RPW];
    float nc[RPW];
#pragma unroll
    for (int r = 0; r < RPW; r++) {
        int n_r = n0 + r;
        int ax  = __shfl_sync(FULL, am.x, r);
        int ay  = __shfl_sync(FULL, am.y, r);
        unsigned bal = __ballot_sync(FULL, lane < NO && osov == (unsigned)n_r);
        int   bo;  float biou;
        if (bal) { bo = 31 - __clz(bal); biou = 1.0f; }  // highest o = last write
        else     { bo = ay; biou = __int_as_float(ax); }
        int l = (biou < 0.5f) ? 0 : __shfl_sync(FULL, olab, bo);
        lbl[r] = l; bo_[r] = bo;
    }

#pragma unroll
    for (int r = 0; r < RPW; r++) {
        float sel = (lbl[r] < 32) ? v0[r] : ((lbl[r] < 64) ? v1[r] : v2[r]);
        float logit = __shfl_sync(FULL, sel, lbl[r] & 31);
        float conf  = __logf(s[r]) - logit;
        nc[r] = (lbl[r] != 0) ? -conf : conf;            // positives stash -conf
    }

    // -------- positives: loc loss + pos_conf (rare path, warp-uniform) -----
    __shared__ float sp[B_T / 32], ss[B_T / 32];
    float myp = 0.0f, mys = 0.0f;
    int cnt = 0;
#pragma unroll
    for (int r = 0; r < RPW; r++) {
        if (lbl[r] != 0) {                               // warp-uniform condition
            cnt++;
            float ax0 = __shfl_sync(FULL, obox.x, bo_[r]);
            float ay0 = __shfl_sync(FULL, obox.y, bo_[r]);
            float ax1 = __shfl_sync(FULL, obox.z, bo_[r]);
            float ay1 = __shfl_sync(FULL, obox.w, bo_[r]);
            float4 d  = __ldg(&dboxes[n0 + r]);
            float bcx = (ax1 + ax0) / 2.0f, bcy = (ay1 + ay0) / 2.0f;
            float bw  = ax1 - ax0,          bh  = ay1 - ay0;
            float tx = (bcx - d.x) / (d.z / 10.0f + 1e-6f);
            float ty = (bcy - d.y) / (d.w / 10.0f + 1e-6f);
            float tz = logf(bw / d.z + 1e-6f) * 5.0f;
            float tw = logf(bh / d.w + 1e-6f) * 5.0f;
            if (lane == 0) {
                myp += -nc[r];                           // recover conf
                float4 lp = __ldg((const float4*)(locs + (size_t)(row0 + r) * 4));
                float acc = 0.0f, dd;
                dd = fabsf(lp.x - tx); acc += (dd < 1.0f) ? 0.5f * dd * dd : dd - 0.5f;
                dd = fabsf(lp.y - ty); acc += (dd < 1.0f) ? 0.5f * dd * dd : dd - 0.5f;
                dd = fabsf(lp.z - tz); acc += (dd < 1.0f) ? 0.5f * dd * dd : dd - 0.5f;
                dd = fabsf(lp.w - tw); acc += (dd < 1.0f) ? 0.5f * dd * dd : dd - 0.5f;
                mys += acc;
            }
            nc[r] = 0.0f;                                // negconf = 0 for positives
        }
    }
    if (lane == 0) {
        ((float4*)g_negconf)[wg] = make_float4(nc[0], nc[1], nc[2], nc[3]);
        sp[wip] = myp; ss[wip] = mys;
        if (cnt) {
            atomicAdd(&g_npos[b], cnt);
            atomicAdd(&g_npos_total, cnt);
        }
    }
    __syncthreads();
    if (threadIdx.x == 0) {
        float tp = 0.0f, ts = 0.0f;
#pragma unroll
        for (int i = 0; i < B_T / 32; i++) { tp += sp[i]; ts += ss[i]; }
        if (tp != 0.0f) atomicAdd(&g_posconf, (double)tp);
        if (ts != 0.0f) atomicAdd(&g_sl1, (double)ts);
    }
}

// ---------------- top-k: register-cached exact 4-pass radix select ---------
// 1024 threads/block, one block per batch. Each thread caches 6 float4 (24
// values) in registers. Histograms: per-warp private 256-bin in shared (no
// cross-warp contention, no collectives). Bin scans: parallel suffix-scan.
#define C_T   1024
#define NA4   (NA / 4)     // 6141 exactly
#define VPT   6            // float4 per thread (6*1024 = 6144 >= 6141)

// sum of 'val' over all threads with tid' > tid (block-wide, all threads call)
__device__ __forceinline__ int block_suffix_after(int val, int tid, int* tmp32)
{
    const unsigned FULL = 0xffffffffu;
    int lane = tid & 31, w = tid >> 5;
    __syncthreads();                       // protect tmp32 reuse
    int s = val;                           // inclusive suffix within warp
#pragma unroll
    for (int o = 1; o < 32; o <<= 1) {
        int v = __shfl_down_sync(FULL, s, o);
        if (lane + o < 32) s += v;
    }
    if (lane == 0) tmp32[w] = s;           // warp totals
    __syncthreads();
    if (tid < 32) {
        int wv = tmp32[tid];
        int t2 = wv;
#pragma unroll
        for (int o = 1; o < 32; o <<= 1) {
            int v = __shfl_down_sync(FULL, t2, o);
            if (lane + o < 32) t2 += v;
        }
        tmp32[tid] = t2 - wv;              // suffix strictly after warp tid
    }
    __syncthreads();
    return tmp32[w] + (s - val);           // later warps + higher lanes in warp
}

__global__ void __launch_bounds__(C_T) k_topk(float* __restrict__ out)
{
    int b = blockIdx.x;
    int tid = threadIdx.x;
    int wid = tid >> 5;

    __shared__ unsigned whist[32][256];    // per-warp private histograms (32KB)
    __shared__ unsigned hist[256];
    __shared__ int      tmp32[32];
    __shared__ int      s_digit, s_rem, s_last;
    __shared__ double   sdbl[32];
    __shared__ int      sint[32];

    int k = 3 * g_npos[b];
    if (k > NA) k = NA;

    if (k > 0) {
        // ---- load once into registers (coalesced) ----
        const float4* v4 = (const float4*)&g_negconf[b * NA];
        float  vals[VPT * 4];
        bool   vok[VPT];
#pragma unroll
        for (int i = 0; i < VPT; i++) {
            int j = tid + i * C_T;
            vok[i] = (j < NA4);
            float4 x = vok[i] ? __ldg(&v4[j]) : make_float4(0.f, 0.f, 0.f, 0.f);
            vals[i * 4 + 0] = x.x; vals[i * 4 + 1] = x.y;
            vals[i * 4 + 2] = x.z; vals[i * 4 + 3] = x.w;
        }

        unsigned prefix = 0, pmask = 0;
        int rem = k;
#pragma unroll
        for (int p = 3; p >= 0; --p) {
            int sh = p * 8;
            // zero per-warp histograms (each thread: 8 entries)
            unsigned* hrow = &whist[0][0];
#pragma unroll
            for (int i = 0; i < 8; i++) hrow[tid + i * C_T] = 0u;
            __syncthreads();
            // histogram from registers into this warp's private row
            unsigned* myh = whist[wid];
#pragma unroll
            for (int i = 0; i < VPT; i++) {
#pragma unroll
                for (int c = 0; c < 4; c++) {
                    unsigned bits = __float_as_uint(vals[i * 4 + c]);
                    if (vok[i] && (bits & pmask) == prefix)
                        atomicAdd(&myh[(bits >> sh) & 255u], 1u);
                }
            }
            __syncthreads();
            // cross-warp reduce: threads 0..255 each own one bin
            int myc = 0;
            if (tid < 256) {
                unsigned c = 0;
#pragma unroll
                for (int w = 0; w < 32; w++) c += whist[w][tid];
                hist[tid] = c;
                myc = (int)c;
            }
            // parallel suffix scan over bins (descending digit order)
            int sufA = block_suffix_after(myc, tid, tmp32);
            if (tid < 256 && sufA < rem && sufA + myc >= rem) {  // unique thread
                s_digit = tid; s_rem = rem - sufA;
            }
            __syncthreads();
            prefix |= ((unsigned)s_digit) << sh;
            pmask  |= 0xFFu << sh;
            rem = s_rem;
            __syncthreads();
        }

        // ---- exact sum of values strictly above the k-th largest ----
        double sg = 0.0; int cg = 0;
#pragma unroll
        for (int i = 0; i < VPT; i++) {
#pragma unroll
            for (int c = 0; c < 4; c++) {
                unsigned bits = __float_as_uint(vals[i * 4 + c]);
                if (vok[i] && bits > prefix) { sg += (double)vals[i * 4 + c]; cg++; }
            }
        }
#pragma unroll
        for (int o = 16; o > 0; o >>= 1) {
            sg += __shfl_xor_sync(0xffffffffu, sg, o);
            cg += __shfl_xor_sync(0xffffffffu, cg, o);
        }
        if ((tid & 31) == 0) { sdbl[wid] = sg; sint[wid] = cg; }
        __syncthreads();
        if (tid == 0) {
            double s2 = 0.0; int c2 = 0;
#pragma unroll
            for (int i = 0; i < 32; i++) { s2 += sdbl[i]; c2 += sint[i]; }
            double t = (double)__uint_as_float(prefix);
            atomicAdd(&g_hard, s2 + (double)(k - c2) * t);   // exact ties
        }
    }

    // completion ticket: last block finalizes the scalar loss
    __threadfence();
    if (tid == 0) {
        int t = atomicAdd(&g_done, 1);
        s_last = (t == BN - 1);
    }
    __syncthreads();
    if (tid == 0 && s_last) {
        double npt  = (double)(*(volatile int*)&g_npos_total);
        double sl1  = *(volatile double*)&g_sl1;
        double pc   = *(volatile double*)&g_posconf;
        double hd   = *(volatile double*)&g_hard;
        double loc  = sl1 / (npt * 4.0);
        double conf = (hd + pc) / npt;
        out[0] = (float)(0.5 * loc + conf);
    }
}

// ---------------- launcher --------------------------------------------------
extern "C" void kernel_launch(void* const* d_in, const int* in_sizes, int n_in,
                              void* d_out, int out_size)
{
    (void)in_sizes; (void)n_in; (void)out_size;
    const float*  locs   = (const float*)d_in[0];
    const float*  cls    = (const float*)d_in[1];
    const float4* boxes  = (const float4*)d_in[2];
    const int*    labels = (const int*)d_in[3];
    const float4* dboxes = (const float4*)d_in[4];

    k_init<<<1, 512>>>();
    dim3 gm((NA + MA_T - 1) / MA_T, BN);
    k_matchA<<<gm, MA_T>>>(boxes, dboxes);
    int blocksB = TOTROWS / (RPW * (B_T / 32));   // 24564, exact
    k_conf<<<blocksB, B_T>>>(cls, locs, boxes, labels, dboxes);
    k_topk<<<BN, C_T>>>((float*)d_out);
}

// round 10
// speedup vs baseline: 1.9844x; 1.1311x over previous
#include <cuda_runtime.h>
#include <math.h>

// Problem constants (fixed shapes from reference setup_inputs)
#define BN   32
#define NA   24564
#define NCLS 81
#define NO   16
#define TOTROWS (BN * NA)   // 786048

// ---------------- scratch (device globals: no allocation allowed) ----------
__device__ float              g_negconf[BN * NA];
__device__ int2               g_argm[BN * NA];     // per-anchor (biou bits, best obj)
__device__ unsigned long long g_best[BN * NO];
__device__ int                g_npos[BN];
__device__ int                g_npos_total;
__device__ int                g_done;
__device__ double             g_posconf;
__device__ double             g_sl1;
__device__ double             g_hard;

// ---------------- init --------------------------------------------------
__global__ void k_init() {
    int i = threadIdx.x;
    if (i < BN * NO) g_best[i] = 0ull;
    if (i < BN)      g_npos[i] = 0;
    if (i == 0) {
        g_npos_total = 0; g_done = 0;
        g_posconf = 0.0; g_sl1 = 0.0; g_hard = 0.0;
    }
}

// ---------------- fused match pass A ---------------------------------------
// 8 anchors per thread; per-object best tracked in REGISTERS across those
// anchors, flushed once per thread via guarded shared atomics. Fast division
// (2-ulp) — feeds only argmax ordering and the 0.5 threshold.
#define MA_T   256
#define MA_A   8
#define MA_BLK (MA_T * MA_A)                   // 2048
#define MA_NB  ((NA + MA_BLK - 1) / MA_BLK)    // 12

__global__ void __launch_bounds__(MA_T) k_matchA(const float4* __restrict__ boxes,
                                                 const float4* __restrict__ dboxes)
{
    int b    = blockIdx.y;
    int base = blockIdx.x * MA_BLK;
    int tid  = threadIdx.x;

    __shared__ float4 sbox[NO];
    __shared__ float  sarea[NO];
    __shared__ unsigned long long sb[NO];
    if (tid < NO) {
        float4 bx = boxes[b * NO + tid];
        sbox[tid]  = bx;
        sarea[tid] = (bx.z - bx.x) * (bx.w - bx.y);
        sb[tid]    = 0ull;
    }
    __syncthreads();

    float    biou_o[NO];
    unsigned bj_o[NO];
#pragma unroll
    for (int o = 0; o < NO; o++) { biou_o[o] = -1.0f; bj_o[o] = 0u; }

#pragma unroll
    for (int i = 0; i < MA_A; i++) {
        int n = base + i * MA_T + tid;                 // coalesced within warp
        if (n < NA) {
            float4 d = __ldg(&dboxes[n]);
            float dx0 = d.x - d.z * 0.5f, dy0 = d.y - d.w * 0.5f;
            float dx1 = d.x + d.z * 0.5f, dy1 = d.y + d.w * 0.5f;
            float areaB = (dx1 - dx0) * (dy1 - dy0);

            float biou = -1.0f; int bo = 0;
#pragma unroll
            for (int o = 0; o < NO; o++) {
                float4 a = sbox[o];
                float ltx = fmaxf(a.x, dx0), lty = fmaxf(a.y, dy0);
                float rbx = fminf(a.z, dx1), rby = fminf(a.w, dy1);
                float w = fmaxf(rbx - ltx, 0.0f), h = fmaxf(rby - lty, 0.0f);
                float inter = w * h;
                float v = __fdividef(inter, sarea[o] + areaB - inter);
                if (v > biou) { biou = v; bo = o; }     // strict >: first max
                if (v > biou_o[o]) { biou_o[o] = v; bj_o[o] = (unsigned)n; }
            }
            g_argm[b * NA + n] = make_int2(__float_as_int(biou), bo);
        }
    }
    // flush per-object bests (once per thread, guarded)
#pragma unroll
    for (int o = 0; o < NO; o++) {
        if (biou_o[o] >= 0.0f) {
            unsigned long long key =
                ((unsigned long long)__float_as_uint(biou_o[o]) << 32) |
                (unsigned long long)(0xFFFFFFFFu - bj_o[o]);
            if (key > sb[o]) atomicMax(&sb[o], key);
        }
    }
    __syncthreads();
    if (tid < NO) {
        unsigned long long k = sb[tid];
        if (k > g_best[b * NO + tid])
            atomicMax(&g_best[b * NO + tid], k);
    }
}

// ------- fused: match-B (override/label/encode) + softmax conf + loc loss --
#define B_T  256
#define RPW  4

__global__ void __launch_bounds__(B_T) k_conf(const float*  __restrict__ cls,
                                              const float*  __restrict__ locs,
                                              const float4* __restrict__ boxes,
                                              const int*    __restrict__ labels,
                                              const float4* __restrict__ dboxes)
{
    const unsigned FULL = 0xffffffffu;
    int wg   = (blockIdx.x * B_T + threadIdx.x) >> 5;   // global warp id
    int lane = threadIdx.x & 31;
    int wip  = threadIdx.x >> 5;
    int row0 = wg * RPW;
    int b    = row0 / NA;          // warp-uniform
    int n0   = row0 - b * NA;

    float4   obox = make_float4(0.f, 0.f, 0.f, 0.f);
    int      olab = 0;
    unsigned osov = 0xFFFFFFFFu;
    if (lane < NO) {
        obox = __ldg(&boxes[b * NO + lane]);
        olab = __ldg(&labels[b * NO + lane]);
        unsigned long long be = g_best[b * NO + lane];
        osov = 0xFFFFFFFFu - (unsigned)(be & 0xFFFFFFFFull);
    }
    int2 am = make_int2(0, 0);
    if (lane < RPW) am = g_argm[row0 + lane];

    // -------- softmax logits (the HBM-dominant part) --------
    const float* p = cls + (size_t)row0 * NCLS;
    float v0[RPW], v1[RPW], v2[RPW];
#pragma unroll
    for (int r = 0; r < RPW; r++) {                      // 12 front-batched LDGs
        v0[r] = __ldg(p + r * NCLS + lane);
        v1[r] = __ldg(p + r * NCLS + 32 + lane);
        v2[r] = (lane < 17) ? __ldg(p + r * NCLS + 64 + lane) : 0.0f;
    }
    float s[RPW];
#pragma unroll
    for (int r = 0; r < RPW; r++)
        s[r] = __expf(v0[r]) + __expf(v1[r]) +
               ((lane < 17) ? __expf(v2[r]) : 0.0f);
#pragma unroll
    for (int o = 16; o > 0; o >>= 1) {                   // 4 interleaved chains
#pragma unroll
        for (int r = 0; r < RPW; r++)
            s[r] += __shfl_xor_sync(FULL, s[r], o);
    }

    // -------- match-B: labels in-register --------
    int   lbl[RPW];
    int   bo_[RPW];
    float nc[RPW];
#pragma unroll
    for (int r = 0; r < RPW; r++) {
        int n_r = n0 + r;
        int ax  = __shfl_sync(FULL, am.x, r);
        int ay  = __shfl_sync(FULL, am.y, r);
        unsigned bal = __ballot_sync(FULL, lane < NO && osov == (unsigned)n_r);
        int   bo;  float biou;
        if (bal) { bo = 31 - __clz(bal); biou = 1.0f; }  // highest o = last write
        else     { bo = ay; biou = __int_as_float(ax); }
        int l = (biou < 0.5f) ? 0 : __shfl_sync(FULL, olab, bo);
        lbl[r] = l; bo_[r] = bo;
    }

#pragma unroll
    for (int r = 0; r < RPW; r++) {
        float sel = (lbl[r] < 32) ? v0[r] : ((lbl[r] < 64) ? v1[r] : v2[r]);
        float logit = __shfl_sync(FULL, sel, lbl[r] & 31);
        float conf  = __logf(s[r]) - logit;
        nc[r] = (lbl[r] != 0) ? -conf : conf;            // positives stash -conf
    }

    // -------- positives: loc loss + pos_conf (rare path, warp-uniform) -----
    __shared__ float sp[B_T / 32], ss[B_T / 32];
    float myp = 0.0f, mys = 0.0f;
    int cnt = 0;
#pragma unroll
    for (int r = 0; r < RPW; r++) {
        if (lbl[r] != 0) {                               // warp-uniform condition
            cnt++;
            float ax0 = __shfl_sync(FULL, obox.x, bo_[r]);
            float ay0 = __shfl_sync(FULL, obox.y, bo_[r]);
            float ax1 = __shfl_sync(FULL, obox.z, bo_[r]);
            float ay1 = __shfl_sync(FULL, obox.w, bo_[r]);
            float4 d  = __ldg(&dboxes[n0 + r]);
            float bcx = (ax1 + ax0) / 2.0f, bcy = (ay1 + ay0) / 2.0f;
            float bw  = ax1 - ax0,          bh  = ay1 - ay0;
            float tx = (bcx - d.x) / (d.z / 10.0f + 1e-6f);
            float ty = (bcy - d.y) / (d.w / 10.0f + 1e-6f);
            float tz = logf(bw / d.z + 1e-6f) * 5.0f;
            float tw = logf(bh / d.w + 1e-6f) * 5.0f;
            if (lane == 0) {
                myp += -nc[r];                           // recover conf
                float4 lp = __ldg((const float4*)(locs + (size_t)(row0 + r) * 4));
                float acc = 0.0f, dd;
                dd = fabsf(lp.x - tx); acc += (dd < 1.0f) ? 0.5f * dd * dd : dd - 0.5f;
                dd = fabsf(lp.y - ty); acc += (dd < 1.0f) ? 0.5f * dd * dd : dd - 0.5f;
                dd = fabsf(lp.z - tz); acc += (dd < 1.0f) ? 0.5f * dd * dd : dd - 0.5f;
                dd = fabsf(lp.w - tw); acc += (dd < 1.0f) ? 0.5f * dd * dd : dd - 0.5f;
                mys += acc;
            }
            nc[r] = 0.0f;                                // negconf = 0 for positives
        }
    }
    if (lane == 0) {
        ((float4*)g_negconf)[wg] = make_float4(nc[0], nc[1], nc[2], nc[3]);
        sp[wip] = myp; ss[wip] = mys;
        if (cnt) {
            atomicAdd(&g_npos[b], cnt);
            atomicAdd(&g_npos_total, cnt);
        }
    }
    __syncthreads();
    if (threadIdx.x == 0) {
        float tp = 0.0f, ts = 0.0f;
#pragma unroll
        for (int i = 0; i < B_T / 32; i++) { tp += sp[i]; ts += ss[i]; }
        if (tp != 0.0f) atomicAdd(&g_posconf, (double)tp);
        if (ts != 0.0f) atomicAdd(&g_sl1, (double)ts);
    }
}

// ---------------- top-k: register-cached exact 4-pass radix select ---------
#define C_T   1024
#define NA4   (NA / 4)     // 6141 exactly
#define VPT   6            // float4 per thread (6*1024 = 6144 >= 6141)

// sum of 'val' over all threads with tid' > tid (block-wide, all threads call)
__device__ __forceinline__ int block_suffix_after(int val, int tid, int* tmp32)
{
    const unsigned FULL = 0xffffffffu;
    int lane = tid & 31, w = tid >> 5;
    __syncthreads();                       // protect tmp32 reuse
    int s = val;                           // inclusive suffix within warp
#pragma unroll
    for (int o = 1; o < 32; o <<= 1) {
        int v = __shfl_down_sync(FULL, s, o);
        if (lane + o < 32) s += v;
    }
    if (lane == 0) tmp32[w] = s;           // warp totals
    __syncthreads();
    if (tid < 32) {
        int wv = tmp32[tid];
        int t2 = wv;
#pragma unroll
        for (int o = 1; o < 32; o <<= 1) {
            int v = __shfl_down_sync(FULL, t2, o);
            if (lane + o < 32) t2 += v;
        }
        tmp32[tid] = t2 - wv;              // suffix strictly after warp tid
    }
    __syncthreads();
    return tmp32[w] + (s - val);           // later warps + higher lanes in warp
}

__global__ void __launch_bounds__(C_T) k_topk(float* __restrict__ out)
{
    int b = blockIdx.x;
    int tid = threadIdx.x;
    int wid = tid >> 5;

    __shared__ unsigned whist[32][256];    // per-warp private histograms (32KB)
    __shared__ unsigned hist[256];
    __shared__ int      tmp32[32];
    __shared__ int      s_digit, s_rem, s_last;
    __shared__ double   sdbl[32];
    __shared__ int      sint[32];

    int k = 3 * g_npos[b];
    if (k > NA) k = NA;

    if (k > 0) {
        // ---- load once into registers (coalesced) ----
        const float4* v4 = (const float4*)&g_negconf[b * NA];
        float  vals[VPT * 4];
        bool   vok[VPT];
#pragma unroll
        for (int i = 0; i < VPT; i++) {
            int j = tid + i * C_T;
            vok[i] = (j < NA4);
            float4 x = vok[i] ? __ldg(&v4[j]) : make_float4(0.f, 0.f, 0.f, 0.f);
            vals[i * 4 + 0] = x.x; vals[i * 4 + 1] = x.y;
            vals[i * 4 + 2] = x.z; vals[i * 4 + 3] = x.w;
        }

        unsigned prefix = 0, pmask = 0;
        int rem = k;
#pragma unroll
        for (int p = 3; p >= 0; --p) {
            int sh = p * 8;
            unsigned* hrow = &whist[0][0];
#pragma unroll
            for (int i = 0; i < 8; i++) hrow[tid + i * C_T] = 0u;
            __syncthreads();
            unsigned* myh = whist[wid];
#pragma unroll
            for (int i = 0; i < VPT; i++) {
#pragma unroll
                for (int c = 0; c < 4; c++) {
                    unsigned bits = __float_as_uint(vals[i * 4 + c]);
                    if (vok[i] && (bits & pmask) == prefix)
                        atomicAdd(&myh[(bits >> sh) & 255u], 1u);
                }
            }
            __syncthreads();
            int myc = 0;
            if (tid < 256) {
                unsigned c = 0;
#pragma unroll
                for (int w = 0; w < 32; w++) c += whist[w][tid];
                hist[tid] = c;
                myc = (int)c;
            }
            int sufA = block_suffix_after(myc, tid, tmp32);
            if (tid < 256 && sufA < rem && sufA + myc >= rem) {  // unique thread
                s_digit = tid; s_rem = rem - sufA;
            }
            __syncthreads();
            prefix |= ((unsigned)s_digit) << sh;
            pmask  |= 0xFFu << sh;
            rem = s_rem;
            __syncthreads();
        }

        // ---- exact sum of values strictly above the k-th largest ----
        double sg = 0.0; int cg = 0;
#pragma unroll
        for (int i = 0; i < VPT; i++) {
#pragma unroll
            for (int c = 0; c < 4; c++) {
                unsigned bits = __float_as_uint(vals[i * 4 + c]);
                if (vok[i] && bits > prefix) { sg += (double)vals[i * 4 + c]; cg++; }
            }
        }
#pragma unroll
        for (int o = 16; o > 0; o >>= 1) {
            sg += __shfl_xor_sync(0xffffffffu, sg, o);
            cg += __shfl_xor_sync(0xffffffffu, cg, o);
        }
        if ((tid & 31) == 0) { sdbl[wid] = sg; sint[wid] = cg; }
        __syncthreads();
        if (tid == 0) {
            double s2 = 0.0; int c2 = 0;
#pragma unroll
            for (int i = 0; i < 32; i++) { s2 += sdbl[i]; c2 += sint[i]; }
            double t = (double)__uint_as_float(prefix);
            atomicAdd(&g_hard, s2 + (double)(k - c2) * t);   // exact ties
        }
    }

    // completion ticket: last block finalizes the scalar loss
    __threadfence();
    if (tid == 0) {
        int t = atomicAdd(&g_done, 1);
        s_last = (t == BN - 1);
    }
    __syncthreads();
    if (tid == 0 && s_last) {
        double npt  = (double)(*(volatile int*)&g_npos_total);
        double sl1  = *(volatile double*)&g_sl1;
        double pc   = *(volatile double*)&g_posconf;
        double hd   = *(volatile double*)&g_hard;
        double loc  = sl1 / (npt * 4.0);
        double conf = (hd + pc) / npt;
        out[0] = (float)(0.5 * loc + conf);
    }
}

// ---------------- launcher --------------------------------------------------
extern "C" void kernel_launch(void* const* d_in, const int* in_sizes, int n_in,
                              void* d_out, int out_size)
{
    (void)in_sizes; (void)n_in; (void)out_size;
    const float*  locs   = (const float*)d_in[0];
    const float*  cls    = (const float*)d_in[1];
    const float4* boxes  = (const float4*)d_in[2];
    const int*    labels = (const int*)d_in[3];
    const float4* dboxes = (const float4*)d_in[4];

    k_init<<<1, 512>>>();
    dim3 gm(MA_NB, BN);
    k_matchA<<<gm, MA_T>>>(boxes, dboxes);
    int blocksB = TOTROWS / (RPW * (B_T / 32));   // 24564, exact
    k_conf<<<blocksB, B_T>>>(cls, locs, boxes, labels, dboxes);
    k_topk<<<BN, C_T>>>((float*)d_out);
}